// round 15
// baseline (speedup 1.0000x reference)
#include <cuda_runtime.h>
#include <cuda_bf16.h>

// ---------------------------------------------------------------------------
// FixedSimpleGNN: 3-layer MPNN, N=100000, E=1000000, H=64.
//   - edges counting-sorted by dst once; k_edge uses sorted lists
//   - per-node a_s/a_d (factorized msg layer-1, bias folded into a_s)
//   - per-edge bf16 mma.m16n8k16 msg layer-2, warp-local
//   - in-warp segmented reduction over sorted dst runs, then v4.bf16x2 red
//   - warp-local bf16 mma update MLP; output head fused into last update
// ---------------------------------------------------------------------------

#define NMAX 100000
#define EMAX 1000000
#define PACKN (3 * 12288 + 2048)
#define NB_SCAN 512   // >= ceil(NMAX/256) = 391

typedef unsigned int uint;

__device__ uint  g_hb [NMAX * 32];
__device__ uint  g_as [NMAX * 32];
__device__ uint  g_ad [NMAX * 32];
__device__ uint  g_agg[NMAX * 32];
__device__ int   g_deg[NMAX];
__device__ int   g_cur[NMAX];
__device__ int   g_bsum[NB_SCAN];
__device__ int   g_ssrc[EMAX];
__device__ int   g_sdst[EMAX];

// packed bf16x2 weights, warp-coalesced B-fragment layout (see k_pack).
__device__ uint p_w[PACKN];

__device__ __forceinline__ uint bpack(float lo, float hi) {
    __nv_bfloat162 p = __floats2bfloat162_rn(lo, hi);
    return *(uint*)&p;
}
__device__ __forceinline__ float2 bunpack(uint v) {
    return __bfloat1622float2(*(__nv_bfloat162*)&v);
}
__device__ __forceinline__ uint badd2(uint a, uint b) {
    __nv_bfloat162 r = __hadd2(*(__nv_bfloat162*)&a, *(__nv_bfloat162*)&b);
    return *(uint*)&r;
}
__device__ __forceinline__ uint brelu2(uint a) {
    __nv_bfloat162 z = __float2bfloat162_rn(0.f);
    __nv_bfloat162 r = __hmax2(*(__nv_bfloat162*)&a, z);
    return *(uint*)&r;
}
__device__ __forceinline__ void mma_bf16(
    float& c0, float& c1, float& c2, float& c3,
    uint a0, uint a1, uint a2, uint a3, uint b0, uint b1)
{
    asm volatile(
        "mma.sync.aligned.m16n8k16.row.col.f32.bf16.bf16.f32 "
        "{%0,%1,%2,%3}, {%4,%5,%6,%7}, {%8,%9}, {%0,%1,%2,%3};"
        : "+f"(c0), "+f"(c1), "+f"(c2), "+f"(c3)
        : "r"(a0), "r"(a1), "r"(a2), "r"(a3), "r"(b0), "r"(b1));
}
__device__ __forceinline__ void red_v4_bf16(uint* addr, uint4 v) {
    asm volatile(
        "red.global.add.noftz.v4.bf16x2 [%0], {%1,%2,%3,%4};"
        :: "l"(addr), "r"(v.x), "r"(v.y), "r"(v.z), "r"(v.w) : "memory");
}
__device__ __forceinline__ void ldsm_x4(
    uint& a0, uint& a1, uint& a2, uint& a3, uint saddr)
{
    asm volatile(
        "ldmatrix.sync.aligned.m8n8.x4.shared.b16 {%0,%1,%2,%3}, [%4];"
        : "=r"(a0), "=r"(a1), "=r"(a2), "=r"(a3) : "r"(saddr));
}
__device__ __forceinline__ uint ldsm_base(const uint* s_u, int stride,
                                          int m0, int lane)
{
    const uint* p = s_u + (m0 + (lane & 15)) * stride + ((lane & 16) >> 2);
    return (uint)__cvta_generic_to_shared(p);
}

// ---------------------------------------------------------------------------
// k_pack: build warp-coalesced bf16x2 weight arrays; also zeroes g_deg.
// ---------------------------------------------------------------------------
__global__ void k_pack(const float* __restrict__ msg_w1,
                       const float* __restrict__ msg_w2,
                       const float* __restrict__ upd_w1,
                       const float* __restrict__ upd_w2,
                       const float* __restrict__ out_w1, int N)
{
    int idx = blockIdx.x * blockDim.x + threadIdx.x;
    if (idx >= PACKN) {
        int i = idx - PACKN;
        if (i < N) g_deg[i] = 0;
        return;
    }
    const float* W;
    int r;
    bool wide = false;
    if (idx >= 3 * 12288) {
        r = idx - 3 * 12288; W = out_w1;
    } else {
        int l = idx / 12288; r = idx % 12288;
        if (r < 4096)       { W = msg_w1 + l * 8192; wide = true; }
        else if (r < 6144)  { r -= 4096;  W = msg_w2 + l * 4096; }
        else if (r < 10240) { r -= 6144;  W = upd_w1 + l * 8192; }
        else                { r -= 10240; W = upd_w2 + l * 4096; }
    }
    int j = r & 3;
    int slot = (r >> 2) & 31;
    int qr = slot & 7, qc = slot >> 3;
    int c, half, kt;
    if (wide) { c = (r >> 7) & 3; half = (r >> 9) & 1; kt = r >> 10; }
    else      { c = (r >> 7) & 1; half = (r >> 8) & 1; kt = r >> 9; }
    int kp = kt * 8 + half * 4 + qc;
    int n = (c * 4 + j) * 8 + qr;
    float lo, hi;
    if (wide && n >= 64) {
        lo = W[(64 + 2*kp) * 64 + (n - 64)];
        hi = W[(64 + 2*kp + 1) * 64 + (n - 64)];
    } else {
        lo = W[(2*kp) * 64 + n];
        hi = W[(2*kp + 1) * 64 + n];
    }
    p_w[idx] = bpack(lo, hi);
}

// ---------------------------------------------------------------------------
// counting sort by dst
// ---------------------------------------------------------------------------
__global__ void k_count(const int* __restrict__ dst, int E) {
    int e = blockIdx.x * blockDim.x + threadIdx.x;
    if (e < E) atomicAdd(&g_deg[dst[e]], 1);
}
__global__ void k_scan1(int N) {
    __shared__ int s[256];
    int tx = threadIdx.x;
    int i = blockIdx.x * 256 + tx;
    s[tx] = (i < N) ? g_deg[i] : 0;
    __syncthreads();
    for (int o = 128; o > 0; o >>= 1) {
        if (tx < o) s[tx] += s[tx + o];
        __syncthreads();
    }
    if (tx == 0) g_bsum[blockIdx.x] = s[0];
}
__global__ void k_scan2(int nb) {
    __shared__ int s[NB_SCAN];
    int tx = threadIdx.x;
    int v = (tx < nb) ? g_bsum[tx] : 0;
    s[tx] = v;
    __syncthreads();
    for (int off = 1; off < NB_SCAN; off <<= 1) {
        int t = (tx >= off) ? s[tx - off] : 0;
        __syncthreads();
        s[tx] += t;
        __syncthreads();
    }
    if (tx < nb) g_bsum[tx] = s[tx] - v;   // exclusive
}
__global__ void k_scan3(int N) {
    __shared__ int s[256];
    int tx = threadIdx.x;
    int i = blockIdx.x * 256 + tx;
    int v = (i < N) ? g_deg[i] : 0;
    s[tx] = v;
    __syncthreads();
    for (int off = 1; off < 256; off <<= 1) {
        int t = (tx >= off) ? s[tx - off] : 0;
        __syncthreads();
        s[tx] += t;
        __syncthreads();
    }
    if (i < N) g_cur[i] = g_bsum[blockIdx.x] + s[tx] - v;   // exclusive prefix
}
__global__ void k_sort(const int* __restrict__ src,
                       const int* __restrict__ dst, int E) {
    int e = blockIdx.x * blockDim.x + threadIdx.x;
    if (e < E) {
        int d = dst[e];
        int p = atomicAdd(&g_cur[d], 1);
        g_ssrc[p] = src[e];
        g_sdst[p] = d;
    }
}

// ---------------------------------------------------------------------------
// pre-phase mma (unchanged)
// ---------------------------------------------------------------------------
__device__ __forceinline__ void pre_mma(
    const uint* s_u, int stride, const uint* pw, const float* __restrict__ b1g,
    int n0, int m0, int lane, int N)
{
    int qrow = lane >> 2, qcol = lane & 3;
    int lslot4 = (qcol * 8 + qrow) * 4;

    float acc[16][4];
#pragma unroll
    for (int nt = 0; nt < 16; nt++)
#pragma unroll
        for (int c = 0; c < 4; c++) acc[nt][c] = 0.f;

    uint sA = ldsm_base(s_u, stride, m0, lane);
#pragma unroll
    for (int kt = 0; kt < 4; kt++) {
        uint a0, a1, a2, a3;
        ldsm_x4(a0, a1, a2, a3, sA + kt * 32);
        const uint* p0 = pw + (kt * 2 + 0) * 512 + lslot4;
        const uint* p1 = pw + (kt * 2 + 1) * 512 + lslot4;
#pragma unroll
        for (int c = 0; c < 4; c++) {
            uint B0[4], B1[4];
            *(uint4*)&B0[0] = __ldg((const uint4*)(p0 + c * 128));
            *(uint4*)&B1[0] = __ldg((const uint4*)(p1 + c * 128));
#pragma unroll
            for (int j = 0; j < 4; j++) {
                int nt = c * 4 + j;
                mma_bf16(acc[nt][0], acc[nt][1], acc[nt][2], acc[nt][3],
                         a0, a1, a2, a3, B0[j], B1[j]);
            }
        }
    }
#pragma unroll
    for (int nt = 0; nt < 16; nt++) {
        int col = nt * 8 + qcol * 2;
        int nA = n0 + m0 + qrow;
        int nB = nA + 8;
        if (col < 64) {
            float bx = __ldg(b1g + col), by = __ldg(b1g + col + 1);
            if (nA < N) g_as[(size_t)nA * 32 + (col >> 1)] =
                bpack(acc[nt][0] + bx, acc[nt][1] + by);
            if (nB < N) g_as[(size_t)nB * 32 + (col >> 1)] =
                bpack(acc[nt][2] + bx, acc[nt][3] + by);
        } else {
            int cp = (col - 64) >> 1;
            if (nA < N) g_ad[(size_t)nA * 32 + cp] = bpack(acc[nt][0], acc[nt][1]);
            if (nB < N) g_ad[(size_t)nB * 32 + cp] = bpack(acc[nt][2], acc[nt][3]);
        }
    }
}

// ---------------------------------------------------------------------------
// encoder (+ fused pre for layer 0)
// ---------------------------------------------------------------------------
__global__ __launch_bounds__(256) void k_encoder(
    const float* __restrict__ x,
    const float* __restrict__ w1, const float* __restrict__ b1,
    const float* __restrict__ w2, const float* __restrict__ b2,
    const float* __restrict__ msg_b1_0, int N)
{
    extern __shared__ float sm[];
    float* s_hid = sm;             // 128 * 65
    float* s_w2  = sm + 128 * 65;  // 64 * 64
    uint*  s_u   = (uint*)sm;      // pre-phase bf16 stage (alias, 128*36)
    __shared__ float s_w1[5 * 64], s_b1[64], s_b2[64];
    __shared__ float s_x[128 * 6];
    int tid = threadIdx.x;
    int n0 = blockIdx.x * 128;

    for (int i = tid; i < 5 * 64; i += 256)  s_w1[i] = w1[i];
    for (int i = tid; i < 64 * 64; i += 256) s_w2[i] = w2[i];
    if (tid < 64) { s_b1[tid] = b1[tid]; s_b2[tid] = b2[tid]; }
    for (int i = tid; i < 128 * 5; i += 256) {
        int r = i / 5, k = i % 5;
        int n = n0 + r;
        s_x[r * 6 + k] = (n < N) ? x[(size_t)n * 5 + k] : 0.f;
    }
#pragma unroll
    for (int i = 0; i < 4; i++) {
        int lin = i * 256 + tid;
        int r = lin >> 3, q = lin & 7;
        int n = n0 + r;
        if (n < N)
            *(uint4*)(g_agg + (size_t)n * 32 + q * 4) = make_uint4(0u, 0u, 0u, 0u);
    }
    __syncthreads();

    int r0 = (tid >> 4) * 8;
    int c0 = (tid & 15) * 4;

    float acc[8][4];
#pragma unroll
    for (int r = 0; r < 8; r++)
#pragma unroll
        for (int c = 0; c < 4; c++) acc[r][c] = 0.f;
#pragma unroll
    for (int k = 0; k < 5; k++) {
        float4 b = *(const float4*)(s_w1 + k * 64 + c0);
#pragma unroll
        for (int r = 0; r < 8; r++) {
            float a = s_x[(r0 + r) * 6 + k];
            acc[r][0] = fmaf(a, b.x, acc[r][0]);
            acc[r][1] = fmaf(a, b.y, acc[r][1]);
            acc[r][2] = fmaf(a, b.z, acc[r][2]);
            acc[r][3] = fmaf(a, b.w, acc[r][3]);
        }
    }
#pragma unroll
    for (int r = 0; r < 8; r++)
#pragma unroll
        for (int c = 0; c < 4; c++)
            s_hid[(r0 + r) * 65 + c0 + c] = fmaxf(acc[r][c] + s_b1[c0 + c], 0.f);
    __syncthreads();

    float acc2[8][4];
#pragma unroll
    for (int r = 0; r < 8; r++)
#pragma unroll
        for (int c = 0; c < 4; c++) acc2[r][c] = 0.f;
#pragma unroll 4
    for (int k = 0; k < 64; k++) {
        float4 b = *(const float4*)(s_w2 + k * 64 + c0);
#pragma unroll
        for (int r = 0; r < 8; r++) {
            float a = s_hid[(r0 + r) * 65 + k];
            acc2[r][0] = fmaf(a, b.x, acc2[r][0]);
            acc2[r][1] = fmaf(a, b.y, acc2[r][1]);
            acc2[r][2] = fmaf(a, b.z, acc2[r][2]);
            acc2[r][3] = fmaf(a, b.w, acc2[r][3]);
        }
    }
    __syncthreads();

    // epilogue: h -> g_hb (bf16 pairs) + s_u
#pragma unroll
    for (int r = 0; r < 8; r++) {
        int n = n0 + r0 + r;
        float vx = fmaxf(acc2[r][0] + s_b2[c0 + 0], 0.f);
        float vy = fmaxf(acc2[r][1] + s_b2[c0 + 1], 0.f);
        float vz = fmaxf(acc2[r][2] + s_b2[c0 + 2], 0.f);
        float vw = fmaxf(acc2[r][3] + s_b2[c0 + 3], 0.f);
        uint plo = bpack(vx, vy), phi = bpack(vz, vw);
        if (n < N) {
            g_hb[(size_t)n * 32 + (c0 >> 1)]     = plo;
            g_hb[(size_t)n * 32 + (c0 >> 1) + 1] = phi;
        }
        s_u[(r0 + r) * 36 + (c0 >> 1)]     = plo;
        s_u[(r0 + r) * 36 + (c0 >> 1) + 1] = phi;
    }
    __syncthreads();

    int warp = tid >> 5, lane = tid & 31;
    pre_mma(s_u, 36, p_w, msg_b1_0, n0, warp * 16, lane, N);
}

// ---------------------------------------------------------------------------
// k_edge: 256 threads, 128 SORTED edges/block, warp-local.
// Scatter = in-warp segmented reduction over dst runs + v4 red from run heads.
// ---------------------------------------------------------------------------
__global__ __launch_bounds__(256, 4) void k_edge(
    int layer, const float* __restrict__ b2, int E)
{
    __shared__ uint s_u[128 * 36];
    __shared__ float s_b2[64];
    int tid = threadIdx.x;
    int e0 = blockIdx.x * 128;
    const uint* pw = p_w + layer * 12288 + 4096;   // msg w2 packed (K=64,N=64)

    if (tid < 64) s_b2[tid] = b2[tid];
    __syncthreads();   // the only block barrier

    int warp = tid >> 5, lane = tid & 31;
    int m0 = warp * 16;

    int sidx = -1, didx = -1;
    {
        int e = e0 + m0 + lane;
        if (lane < 16 && e < E) { sidx = g_ssrc[e]; didx = g_sdst[e]; }
    }

    // gather + layer-1: 16 edges x 8 uint4 = 128 tasks / 32 lanes
#pragma unroll
    for (int i = 0; i < 4; i++) {
        int t = i * 32 + lane;
        int el = t >> 3, q = t & 7;
        int s = __shfl_sync(0xffffffffu, sidx, el);   // convergent
        int d = __shfl_sync(0xffffffffu, didx, el);   // convergent
        uint4 v = make_uint4(0u, 0u, 0u, 0u);
        if (s >= 0) {
            uint4 a = __ldg((const uint4*)(g_as + (size_t)s * 32 + q * 4));
            uint4 b = __ldg((const uint4*)(g_ad + (size_t)d * 32 + q * 4));
            v.x = brelu2(badd2(a.x, b.x));
            v.y = brelu2(badd2(a.y, b.y));
            v.z = brelu2(badd2(a.z, b.z));
            v.w = brelu2(badd2(a.w, b.w));
        }
        *(uint4*)(s_u + (m0 + el) * 36 + q * 4) = v;
    }
    __syncwarp();

    int qrow = lane >> 2, qcol = lane & 3;
    int lslot4 = (qcol * 8 + qrow) * 4;

    float acc[8][4];
#pragma unroll
    for (int nt = 0; nt < 8; nt++)
#pragma unroll
        for (int c = 0; c < 4; c++) acc[nt][c] = 0.f;

    uint sA = ldsm_base(s_u, 36, m0, lane);
#pragma unroll
    for (int kt = 0; kt < 4; kt++) {
        uint a0, a1, a2, a3;
        ldsm_x4(a0, a1, a2, a3, sA + kt * 32);
        const uint* p0 = pw + (kt * 2 + 0) * 256 + lslot4;
        const uint* p1 = pw + (kt * 2 + 1) * 256 + lslot4;
#pragma unroll
        for (int c = 0; c < 2; c++) {
            uint B0[4], B1[4];
            *(uint4*)&B0[0] = __ldg((const uint4*)(p0 + c * 128));
            *(uint4*)&B1[0] = __ldg((const uint4*)(p1 + c * 128));
#pragma unroll
            for (int j = 0; j < 4; j++) {
                int nt = c * 4 + j;
                mma_bf16(acc[nt][0], acc[nt][1], acc[nt][2], acc[nt][3],
                         a0, a1, a2, a3, B0[j], B1[j]);
            }
        }
    }
    __syncwarp();

    // epilogue: m = relu(acc + b2) -> own rows
#pragma unroll
    for (int nt = 0; nt < 8; nt++) {
        int c = nt * 8 + qcol * 2;
        float bx = s_b2[c], by = s_b2[c + 1];
        int cp = nt * 4 + qcol;
        s_u[(m0 + qrow) * 36 + cp] =
            bpack(fmaxf(acc[nt][0] + bx, 0.f), fmaxf(acc[nt][1] + by, 0.f));
        s_u[(m0 + qrow + 8) * 36 + cp] =
            bpack(fmaxf(acc[nt][2] + bx, 0.f), fmaxf(acc[nt][3] + by, 0.f));
    }
    __syncwarp();

    // scatter with segmented reduction: dst sorted -> runs of equal d.
    // lanes 0-15 handle quarter q0 of edge el=lane; lanes 16-31 quarter q0+1.
    int el = lane & 15;
    int d  = __shfl_sync(0xffffffffu, didx, el);
    int dp = __shfl_up_sync(0xffffffffu, d, 1, 16);
    bool head = (el == 0) || (dp != d);
    int qh = lane >> 4;
#pragma unroll
    for (int p = 0; p < 4; p++) {
        int q = p * 2 + qh;
        uint4 v = *(const uint4*)(s_u + (m0 + el) * 36 + q * 4);
        // segmented suffix sum within runs (width-16 halves)
#pragma unroll
        for (int s = 1; s < 16; s <<= 1) {
            uint wx = __shfl_down_sync(0xffffffffu, v.x, s, 16);
            uint wy = __shfl_down_sync(0xffffffffu, v.y, s, 16);
            uint wz = __shfl_down_sync(0xffffffffu, v.z, s, 16);
            uint ww = __shfl_down_sync(0xffffffffu, v.w, s, 16);
            int  ds = __shfl_down_sync(0xffffffffu, d, s, 16);
            if ((el + s < 16) && (ds == d)) {
                v.x = badd2(v.x, wx);
                v.y = badd2(v.y, wy);
                v.z = badd2(v.z, wz);
                v.w = badd2(v.w, ww);
            }
        }
        if (head && d >= 0)
            red_v4_bf16(g_agg + (size_t)d * 32 + q * 4, v);
    }
}

// ---------------------------------------------------------------------------
// k_upd: warp-local. h = mlp2(concat(h, agg/deg)); zeroes g_agg rows;
// if has_next: fused pre for layer+1; else: fused output head.
// ---------------------------------------------------------------------------
__global__ __launch_bounds__(256, 3) void k_upd(
    int layer, const float* __restrict__ b1, const float* __restrict__ b2,
    int has_next, const float* __restrict__ msg_b1_next,
    const float* __restrict__ ob1, const float* __restrict__ ow2,
    const float* __restrict__ ob2, float* __restrict__ outp, int N)
{
    __shared__ uint s_u[128 * 68];
    __shared__ float s_b1[64], s_b2[64];
    __shared__ float s_ob1[64], s_ow2[192], s_ob2[3];
    int tid = threadIdx.x;
    int n0 = blockIdx.x * 128;
    int is_last = !has_next;
    const uint* pw1 = p_w + layer * 12288 + 6144;
    const uint* pw2 = p_w + layer * 12288 + 10240;

    if (tid < 64) { s_b1[tid] = b1[tid]; s_b2[tid] = b2[tid]; }
    if (is_last) {
        if (tid >= 64 && tid < 128) s_ob1[tid - 64] = ob1[tid - 64];
        if (tid >= 128 && tid < 224) {
            s_ow2[tid - 128] = ow2[tid - 128];
            s_ow2[tid - 128 + 96] = ow2[tid - 128 + 96];
        }
        if (tid >= 224 && tid < 227) s_ob2[tid - 224] = ob2[tid - 224];
    }
    __syncthreads();

    int warp = tid >> 5, lane = tid & 31;
    int m0 = warp * 16;

    float ivreg = 1.f;
    if (lane < 16) {
        int n = n0 + m0 + lane;
        if (n < N) ivreg = 1.f / fmaxf((float)__ldg(g_deg + n), 1.f);
    }

#pragma unroll
    for (int i = 0; i < 8; i++) {
        int t = i * 32 + lane;
        int rl = t >> 4, q = t & 15;
        float iv = __shfl_sync(0xffffffffu, ivreg, rl);   // convergent
        int n = n0 + m0 + rl;
        uint4 v = make_uint4(0u, 0u, 0u, 0u);
        if (n < N) {
            if (q < 8) {
                v = *(const uint4*)(g_hb + (size_t)n * 32 + q * 4);
            } else {
                int qq = q - 8;
                uint4 a = *(const uint4*)(g_agg + (size_t)n * 32 + qq * 4);
                float2 p0 = bunpack(a.x), p1 = bunpack(a.y);
                float2 p2 = bunpack(a.z), p3 = bunpack(a.w);
                v.x = bpack(p0.x * iv, p0.y * iv);
                v.y = bpack(p1.x * iv, p1.y * iv);
                v.z = bpack(p2.x * iv, p2.y * iv);
                v.w = bpack(p3.x * iv, p3.y * iv);
                *(uint4*)(g_agg + (size_t)n * 32 + qq * 4) = make_uint4(0u, 0u, 0u, 0u);
            }
        }
        *(uint4*)(s_u + (m0 + rl) * 68 + q * 4) = v;
    }
    __syncwarp();

    int qrow = lane >> 2, qcol = lane & 3;
    int lslot4 = (qcol * 8 + qrow) * 4;
    uint sA = ldsm_base(s_u, 68, m0, lane);

    // phase 1: K=128
    float acc[8][4];
#pragma unroll
    for (int nt = 0; nt < 8; nt++)
#pragma unroll
        for (int c = 0; c < 4; c++) acc[nt][c] = 0.f;
#pragma unroll
    for (int kt = 0; kt < 8; kt++) {
        uint a0, a1, a2, a3;
        ldsm_x4(a0, a1, a2, a3, sA + kt * 32);
        const uint* p0 = pw1 + (kt * 2 + 0) * 256 + lslot4;
        const uint* p1 = pw1 + (kt * 2 + 1) * 256 + lslot4;
#pragma unroll
        for (int c = 0; c < 2; c++) {
            uint B0[4], B1[4];
            *(uint4*)&B0[0] = __ldg((const uint4*)(p0 + c * 128));
            *(uint4*)&B1[0] = __ldg((const uint4*)(p1 + c * 128));
#pragma unroll
            for (int j = 0; j < 4; j++) {
                int nt = c * 4 + j;
                mma_bf16(acc[nt][0], acc[nt][1], acc[nt][2], acc[nt][3],
                         a0, a1, a2, a3, B0[j], B1[j]);
            }
        }
    }
    __syncwarp();

    // hidden -> slab offset 32
#pragma unroll
    for (int nt = 0; nt < 8; nt++) {
        int c = nt * 8 + qcol * 2;
        float bx = s_b1[c], by = s_b1[c + 1];
        int cp = 32 + nt * 4 + qcol;
        s_u[(m0 + qrow) * 68 + cp] =
            bpack(fmaxf(acc[nt][0] + bx, 0.f), fmaxf(acc[nt][1] + by, 0.f));
        s_u[(m0 + qrow + 8) * 68 + cp] =
            bpack(fmaxf(acc[nt][2] + bx, 0.f), fmaxf(acc[nt][3] + by, 0.f));
    }
    __syncwarp();

    // phase 2: K=64
    float acc2[8][4];
#pragma unroll
    for (int nt = 0; nt < 8; nt++)
#pragma unroll
        for (int c = 0; c < 4; c++) acc2[nt][c] = 0.f;
#pragma unroll
    for (int kt = 0; kt < 4; kt++) {
        uint a0, a1, a2, a3;
        ldsm_x4(a0, a1, a2, a3, sA + 128 + kt * 32);
        const uint* p0 = pw2 + (kt * 2 + 0) * 256 + lslot4;
        const uint* p1 = pw2 + (kt * 2 + 1) * 256 + lslot4;
#pragma unroll
        for (int c = 0; c < 2; c++) {
            uint B0[4], B1[4];
            *(uint4*)&B0[0] = __ldg((const uint4*)(p0 + c * 128));
            *(uint4*)&B1[0] = __ldg((const uint4*)(p1 + c * 128));
#pragma unroll
            for (int j = 0; j < 4; j++) {
                int nt = c * 4 + j;
                mma_bf16(acc2[nt][0], acc2[nt][1], acc2[nt][2], acc2[nt][3],
                         a0, a1, a2, a3, B0[j], B1[j]);
            }
        }
    }
    __syncwarp();

    // h -> slab offset 0 + g_hb (if not last)
#pragma unroll
    for (int nt = 0; nt < 8; nt++) {
        int c = nt * 8 + qcol * 2;
        float bx = s_b2[c], by = s_b2[c + 1];
        int cp = nt * 4 + qcol;
        int nA = n0 + m0 + qrow;
        int nB = nA + 8;
        uint pA = bpack(fmaxf(acc2[nt][0] + bx, 0.f), fmaxf(acc2[nt][1] + by, 0.f));
        uint pB = bpack(fmaxf(acc2[nt][2] + bx, 0.f), fmaxf(acc2[nt][3] + by, 0.f));
        s_u[(m0 + qrow) * 68 + cp]     = pA;
        s_u[(m0 + qrow + 8) * 68 + cp] = pB;
        if (!is_last) {
            if (nA < N) g_hb[(size_t)nA * 32 + cp] = pA;
            if (nB < N) g_hb[(size_t)nB * 32 + cp] = pB;
        }
    }
    __syncwarp();

    if (has_next) {
        pre_mma(s_u, 68, p_w + (layer + 1) * 12288, msg_b1_next,
                n0, m0, lane, N);
        return;
    }

    // ---- fused output head ----
    const uint* pw3 = p_w + 3 * 12288;
    float acc3[8][4];
#pragma unroll
    for (int nt = 0; nt < 8; nt++)
#pragma unroll
        for (int c = 0; c < 4; c++) acc3[nt][c] = 0.f;
#pragma unroll
    for (int kt = 0; kt < 4; kt++) {
        uint a0, a1, a2, a3;
        ldsm_x4(a0, a1, a2, a3, sA + kt * 32);
        const uint* p0 = pw3 + (kt * 2 + 0) * 256 + lslot4;
        const uint* p1 = pw3 + (kt * 2 + 1) * 256 + lslot4;
#pragma unroll
        for (int c = 0; c < 2; c++) {
            uint B0[4], B1[4];
            *(uint4*)&B0[0] = __ldg((const uint4*)(p0 + c * 128));
            *(uint4*)&B1[0] = __ldg((const uint4*)(p1 + c * 128));
#pragma unroll
            for (int j = 0; j < 4; j++) {
                int nt = c * 4 + j;
                mma_bf16(acc3[nt][0], acc3[nt][1], acc3[nt][2], acc3[nt][3],
                         a0, a1, a2, a3, B0[j], B1[j]);
            }
        }
    }

    float pA[3] = {0.f, 0.f, 0.f}, pB[3] = {0.f, 0.f, 0.f};
#pragma unroll
    for (int nt = 0; nt < 8; nt++) {
        int c = nt * 8 + qcol * 2;
        float o1a = s_ob1[c], o1b = s_ob1[c + 1];
        float hA0 = fmaxf(acc3[nt][0] + o1a, 0.f);
        float hA1 = fmaxf(acc3[nt][1] + o1b, 0.f);
        float hB0 = fmaxf(acc3[nt][2] + o1a, 0.f);
        float hB1 = fmaxf(acc3[nt][3] + o1b, 0.f);
#pragma unroll
        for (int cc = 0; cc < 3; cc++) {
            float w0 = s_ow2[c * 3 + cc], w1v = s_ow2[(c + 1) * 3 + cc];
            pA[cc] = fmaf(hA0, w0, fmaf(hA1, w1v, pA[cc]));
            pB[cc] = fmaf(hB0, w0, fmaf(hB1, w1v, pB[cc]));
        }
    }
#pragma unroll
    for (int cc = 0; cc < 3; cc++) {
        pA[cc] += __shfl_xor_sync(0xffffffffu, pA[cc], 1);
        pA[cc] += __shfl_xor_sync(0xffffffffu, pA[cc], 2);
        pB[cc] += __shfl_xor_sync(0xffffffffu, pB[cc], 1);
        pB[cc] += __shfl_xor_sync(0xffffffffu, pB[cc], 2);
    }
    if (qcol == 0) {
        int nA = n0 + m0 + qrow;
        int nB = nA + 8;
        if (nA < N) {
#pragma unroll
            for (int cc = 0; cc < 3; cc++)
                outp[(size_t)nA * 3 + cc] =
                    6.283185307179586f / (1.f + expf(-(pA[cc] + s_ob2[cc])));
        }
        if (nB < N) {
#pragma unroll
            for (int cc = 0; cc < 3; cc++)
                outp[(size_t)nB * 3 + cc] =
                    6.283185307179586f / (1.f + expf(-(pB[cc] + s_ob2[cc])));
        }
    }
}

// ---------------------------------------------------------------------------
extern "C" void kernel_launch(void* const* d_in, const int* in_sizes, int n_in,
                              void* d_out, int out_size)
{
    const float* x      = (const float*)d_in[0];
    const int*   ei     = (const int*)  d_in[1];
    const float* enc_w1 = (const float*)d_in[2];
    const float* enc_b1 = (const float*)d_in[3];
    const float* enc_w2 = (const float*)d_in[4];
    const float* enc_b2 = (const float*)d_in[5];
    const float* msg_w1 = (const float*)d_in[6];
    const float* msg_b1 = (const float*)d_in[7];
    const float* msg_w2 = (const float*)d_in[8];
    const float* msg_b2 = (const float*)d_in[9];
    const float* upd_w1 = (const float*)d_in[10];
    const float* upd_b1 = (const float*)d_in[11];
    const float* upd_w2 = (const float*)d_in[12];
    const float* upd_b2 = (const float*)d_in[13];
    const float* out_w1 = (const float*)d_in[14];
    const float* out_b1 = (const float*)d_in[15];
    const float* out_w2 = (const float*)d_in[16];
    const float* out_b2 = (const float*)d_in[17];

    int N = in_sizes[0] / 5;
    int E = in_sizes[1] / 2;
    if (N > NMAX) N = NMAX;
    if (E > EMAX) E = EMAX;
    const int* src = ei;
    const int* dstp = ei + E;

    const int ENC_SM = (128 * 65 + 64 * 64) * 4;    // 49664
    cudaFuncSetAttribute(k_encoder, cudaFuncAttributeMaxDynamicSharedMemorySize, ENC_SM);

    int nbE256 = (E + 255) / 256;
    int nbN128 = (N + 127) / 128;
    int nbN256 = (N + 255) / 256;
    int nbE128 = (E + 127) / 128;

    k_pack<<<(PACKN + N + 255) / 256, 256>>>(msg_w1, msg_w2, upd_w1, upd_w2,
                                             out_w1, N);
    k_count<<<nbE256, 256>>>(dstp, E);
    k_scan1<<<nbN256, 256>>>(N);
    k_scan2<<<1, NB_SCAN>>>(nbN256);
    k_scan3<<<nbN256, 256>>>(N);
    k_sort<<<nbE256, 256>>>(src, dstp, E);
    k_encoder<<<nbN128, 256, ENC_SM>>>(x, enc_w1, enc_b1, enc_w2, enc_b2,
                                       msg_b1, N);

    for (int l = 0; l < 3; l++) {
        k_edge<<<nbE128, 256>>>(l, msg_b2 + l * 64, E);
        k_upd<<<nbN128, 256>>>(l, upd_b1 + l * 64, upd_b2 + l * 64,
                               (l < 2) ? 1 : 0, msg_b1 + (l + 1) * 64,
                               out_b1, out_w2, out_b2, (float*)d_out, N);
    }
}

// round 16
// speedup vs baseline: 1.0863x; 1.0863x over previous
#include <cuda_runtime.h>
#include <cuda_bf16.h>

// ---------------------------------------------------------------------------
// FixedSimpleGNN: 3-layer MPNN, N=100000, E=1000000, H=64.
//   - per-node a_s/a_d (factorized msg layer-1, bias folded into a_s)
//   - per-edge bf16 mma.m16n8k16 msg layer-2, warp-local
//   - v4.bf16x2 red scatter (unsorted edges; sort reverted per R15 post-mortem)
//   - warp-local bf16 mma update MLP; output head fused into last update
//   - encoder layer-2 on tensor cores (packed enc_w2), fused pre-phase
// ---------------------------------------------------------------------------

#define NMAX 100000
#define EMAX 1000000
#define PACKN (3 * 12288 + 4096)

typedef unsigned int uint;

__device__ uint  g_hb [NMAX * 32];   // h, bf16x2 pairs
__device__ uint  g_as [NMAX * 32];   // bf16x2 pairs (msg_b1 folded in)
__device__ uint  g_ad [NMAX * 32];   // bf16x2 pairs
__device__ uint  g_agg[NMAX * 32];   // bf16x2 pairs (atomic accum)
__device__ float g_cnt[NMAX];

// packed bf16x2 weights, warp-coalesced B-fragment layout (see k_pack):
//   per layer l*12288: +0 msg W' (N=128) | +4096 msg w2 | +6144 upd w1 | +10240 upd w2
//   +36864 out w1 | +38912 enc w2
__device__ uint p_w[PACKN];

__device__ __forceinline__ uint bpack(float lo, float hi) {
    __nv_bfloat162 p = __floats2bfloat162_rn(lo, hi);
    return *(uint*)&p;
}
__device__ __forceinline__ float2 bunpack(uint v) {
    return __bfloat1622float2(*(__nv_bfloat162*)&v);
}
__device__ __forceinline__ uint badd2(uint a, uint b) {
    __nv_bfloat162 r = __hadd2(*(__nv_bfloat162*)&a, *(__nv_bfloat162*)&b);
    return *(uint*)&r;
}
__device__ __forceinline__ uint brelu2(uint a) {
    __nv_bfloat162 z = __float2bfloat162_rn(0.f);
    __nv_bfloat162 r = __hmax2(*(__nv_bfloat162*)&a, z);
    return *(uint*)&r;
}
__device__ __forceinline__ void mma_bf16(
    float& c0, float& c1, float& c2, float& c3,
    uint a0, uint a1, uint a2, uint a3, uint b0, uint b1)
{
    asm volatile(
        "mma.sync.aligned.m16n8k16.row.col.f32.bf16.bf16.f32 "
        "{%0,%1,%2,%3}, {%4,%5,%6,%7}, {%8,%9}, {%0,%1,%2,%3};"
        : "+f"(c0), "+f"(c1), "+f"(c2), "+f"(c3)
        : "r"(a0), "r"(a1), "r"(a2), "r"(a3), "r"(b0), "r"(b1));
}
__device__ __forceinline__ void red_v4_bf16(uint* addr, uint4 v) {
    asm volatile(
        "red.global.add.noftz.v4.bf16x2 [%0], {%1,%2,%3,%4};"
        :: "l"(addr), "r"(v.x), "r"(v.y), "r"(v.z), "r"(v.w) : "memory");
}
__device__ __forceinline__ void ldsm_x4(
    uint& a0, uint& a1, uint& a2, uint& a3, uint saddr)
{
    asm volatile(
        "ldmatrix.sync.aligned.m8n8.x4.shared.b16 {%0,%1,%2,%3}, [%4];"
        : "=r"(a0), "=r"(a1), "=r"(a2), "=r"(a3) : "r"(saddr));
}
__device__ __forceinline__ uint ldsm_base(const uint* s_u, int stride,
                                          int m0, int lane)
{
    const uint* p = s_u + (m0 + (lane & 15)) * stride + ((lane & 16) >> 2);
    return (uint)__cvta_generic_to_shared(p);
}

// ---------------------------------------------------------------------------
// k_pack: build warp-coalesced bf16x2 weight arrays; also zeroes g_cnt.
// Layout per K x 64 block (2048 uints): addr = ((kt*2+half)*2+c)*128 +
//   (qc*8+qr)*4 + j; pair(W[2kp][n], W[2kp+1][n]), kp=kt*8+half*4+qc,
//   n=(c*4+j)*8+qr. msg W' (N=128): c in [0,4), group stride 512.
// ---------------------------------------------------------------------------
__global__ void k_pack(const float* __restrict__ msg_w1,
                       const float* __restrict__ msg_w2,
                       const float* __restrict__ upd_w1,
                       const float* __restrict__ upd_w2,
                       const float* __restrict__ out_w1,
                       const float* __restrict__ enc_w2, int N)
{
    int idx = blockIdx.x * blockDim.x + threadIdx.x;
    if (idx >= PACKN) {
        int i = idx - PACKN;
        if (i < N) g_cnt[i] = 0.f;
        return;
    }
    const float* W;
    int r;
    bool wide = false;
    if (idx >= 3 * 12288 + 2048) {
        r = idx - (3 * 12288 + 2048); W = enc_w2;
    } else if (idx >= 3 * 12288) {
        r = idx - 3 * 12288; W = out_w1;
    } else {
        int l = idx / 12288; r = idx % 12288;
        if (r < 4096)       { W = msg_w1 + l * 8192; wide = true; }
        else if (r < 6144)  { r -= 4096;  W = msg_w2 + l * 4096; }
        else if (r < 10240) { r -= 6144;  W = upd_w1 + l * 8192; }
        else                { r -= 10240; W = upd_w2 + l * 4096; }
    }
    int j = r & 3;
    int slot = (r >> 2) & 31;
    int qr = slot & 7, qc = slot >> 3;
    int c, half, kt;
    if (wide) { c = (r >> 7) & 3; half = (r >> 9) & 1; kt = r >> 10; }
    else      { c = (r >> 7) & 1; half = (r >> 8) & 1; kt = r >> 9; }
    int kp = kt * 8 + half * 4 + qc;
    int n = (c * 4 + j) * 8 + qr;
    float lo, hi;
    if (wide && n >= 64) {
        lo = W[(64 + 2*kp) * 64 + (n - 64)];
        hi = W[(64 + 2*kp + 1) * 64 + (n - 64)];
    } else {
        lo = W[(2*kp) * 64 + n];
        hi = W[(2*kp + 1) * 64 + n];
    }
    p_w[idx] = bpack(lo, hi);
}

// ---------------------------------------------------------------------------
__global__ void k_count(const int* __restrict__ dst, int E) {
    int e = blockIdx.x * blockDim.x + threadIdx.x;
    if (e < E) atomicAdd(&g_cnt[dst[e]], 1.f);
}

// ---------------------------------------------------------------------------
// pre-phase mma: A = bf16 h pairs in s_u (offset 0, given stride),
// B = W' (K=64, N=128) packed. Warp covers rows m0..m0+15, 128 cols.
// msg_b1 of the target layer is folded into the a_s half.
// ---------------------------------------------------------------------------
__device__ __forceinline__ void pre_mma(
    const uint* s_u, int stride, const uint* pw, const float* __restrict__ b1g,
    int n0, int m0, int lane, int N)
{
    int qrow = lane >> 2, qcol = lane & 3;
    int lslot4 = (qcol * 8 + qrow) * 4;

    float acc[16][4];
#pragma unroll
    for (int nt = 0; nt < 16; nt++)
#pragma unroll
        for (int c = 0; c < 4; c++) acc[nt][c] = 0.f;

    uint sA = ldsm_base(s_u, stride, m0, lane);
#pragma unroll
    for (int kt = 0; kt < 4; kt++) {
        uint a0, a1, a2, a3;
        ldsm_x4(a0, a1, a2, a3, sA + kt * 32);
        const uint* p0 = pw + (kt * 2 + 0) * 512 + lslot4;
        const uint* p1 = pw + (kt * 2 + 1) * 512 + lslot4;
#pragma unroll
        for (int c = 0; c < 4; c++) {
            uint B0[4], B1[4];
            *(uint4*)&B0[0] = __ldg((const uint4*)(p0 + c * 128));
            *(uint4*)&B1[0] = __ldg((const uint4*)(p1 + c * 128));
#pragma unroll
            for (int j = 0; j < 4; j++) {
                int nt = c * 4 + j;
                mma_bf16(acc[nt][0], acc[nt][1], acc[nt][2], acc[nt][3],
                         a0, a1, a2, a3, B0[j], B1[j]);
            }
        }
    }
#pragma unroll
    for (int nt = 0; nt < 16; nt++) {
        int col = nt * 8 + qcol * 2;
        int nA = n0 + m0 + qrow;
        int nB = nA + 8;
        if (col < 64) {
            float bx = __ldg(b1g + col), by = __ldg(b1g + col + 1);
            if (nA < N) g_as[(size_t)nA * 32 + (col >> 1)] =
                bpack(acc[nt][0] + bx, acc[nt][1] + by);
            if (nB < N) g_as[(size_t)nB * 32 + (col >> 1)] =
                bpack(acc[nt][2] + bx, acc[nt][3] + by);
        } else {
            int cp = (col - 64) >> 1;
            if (nA < N) g_ad[(size_t)nA * 32 + cp] = bpack(acc[nt][0], acc[nt][1]);
            if (nB < N) g_ad[(size_t)nB * 32 + cp] = bpack(acc[nt][2], acc[nt][3]);
        }
    }
}

// ---------------------------------------------------------------------------
// encoder (mma version): layer1 scalar (K=5) -> bf16 hidden (slab offset 32),
// layer2 via packed enc_w2 mma -> h (slab offset 0 + g_hb), fused pre_mma.
// Slab: 128 rows x 68 uints. Zeroes g_agg.
// ---------------------------------------------------------------------------
__global__ __launch_bounds__(256) void k_encoder(
    const float* __restrict__ x,
    const float* __restrict__ w1, const float* __restrict__ b1,
    const float* __restrict__ b2,
    const float* __restrict__ msg_b1_0, int N)
{
    __shared__ uint s_u[128 * 68];
    __shared__ float s_w1[5 * 64], s_b1[64], s_b2[64];
    int tid = threadIdx.x;
    int n0 = blockIdx.x * 128;

    for (int i = tid; i < 5 * 64; i += 256) s_w1[i] = w1[i];
    if (tid < 64) { s_b1[tid] = b1[tid]; s_b2[tid] = b2[tid]; }
#pragma unroll
    for (int i = 0; i < 4; i++) {
        int lin = i * 256 + tid;
        int r = lin >> 3, q = lin & 7;
        int n = n0 + r;
        if (n < N)
            *(uint4*)(g_agg + (size_t)n * 32 + q * 4) = make_uint4(0u, 0u, 0u, 0u);
    }
    __syncthreads();

    // layer 1: thread handles row (tid & 127), cols half*32..+32
    {
        int row = tid & 127, half = tid >> 7;
        int n = n0 + row;
        float xv[5];
#pragma unroll
        for (int k = 0; k < 5; k++)
            xv[k] = (n < N) ? __ldg(x + (size_t)n * 5 + k) : 0.f;
#pragma unroll
        for (int j = 0; j < 32; j += 2) {
            int c = half * 32 + j;
            float v0 = s_b1[c], v1 = s_b1[c + 1];
#pragma unroll
            for (int k = 0; k < 5; k++) {
                v0 = fmaf(xv[k], s_w1[k * 64 + c], v0);
                v1 = fmaf(xv[k], s_w1[k * 64 + c + 1], v1);
            }
            s_u[row * 68 + 32 + (c >> 1)] =
                bpack(fmaxf(v0, 0.f), fmaxf(v1, 0.f));
        }
    }
    __syncthreads();

    int warp = tid >> 5, lane = tid & 31;
    int m0 = warp * 16;
    int qrow = lane >> 2, qcol = lane & 3;
    int lslot4 = (qcol * 8 + qrow) * 4;
    uint sA = ldsm_base(s_u, 68, m0, lane);
    const uint* pw2 = p_w + 3 * 12288 + 2048;   // enc w2 packed (K=64,N=64)

    // layer 2: K=64 (hidden at offset 32)
    float acc[8][4];
#pragma unroll
    for (int nt = 0; nt < 8; nt++)
#pragma unroll
        for (int c = 0; c < 4; c++) acc[nt][c] = 0.f;
#pragma unroll
    for (int kt = 0; kt < 4; kt++) {
        uint a0, a1, a2, a3;
        ldsm_x4(a0, a1, a2, a3, sA + 128 + kt * 32);
        const uint* p0 = pw2 + (kt * 2 + 0) * 256 + lslot4;
        const uint* p1 = pw2 + (kt * 2 + 1) * 256 + lslot4;
#pragma unroll
        for (int c = 0; c < 2; c++) {
            uint B0[4], B1[4];
            *(uint4*)&B0[0] = __ldg((const uint4*)(p0 + c * 128));
            *(uint4*)&B1[0] = __ldg((const uint4*)(p1 + c * 128));
#pragma unroll
            for (int j = 0; j < 4; j++) {
                int nt = c * 4 + j;
                mma_bf16(acc[nt][0], acc[nt][1], acc[nt][2], acc[nt][3],
                         a0, a1, a2, a3, B0[j], B1[j]);
            }
        }
    }
    __syncwarp();

    // h = relu(acc + b2) -> slab offset 0 + g_hb
#pragma unroll
    for (int nt = 0; nt < 8; nt++) {
        int c = nt * 8 + qcol * 2;
        float bx = s_b2[c], by = s_b2[c + 1];
        int cp = nt * 4 + qcol;
        int nA = n0 + m0 + qrow;
        int nB = nA + 8;
        uint pA = bpack(fmaxf(acc[nt][0] + bx, 0.f), fmaxf(acc[nt][1] + by, 0.f));
        uint pB = bpack(fmaxf(acc[nt][2] + bx, 0.f), fmaxf(acc[nt][3] + by, 0.f));
        s_u[(m0 + qrow) * 68 + cp]     = pA;
        s_u[(m0 + qrow + 8) * 68 + cp] = pB;
        if (nA < N) g_hb[(size_t)nA * 32 + cp] = pA;
        if (nB < N) g_hb[(size_t)nB * 32 + cp] = pB;
    }
    __syncwarp();

    pre_mma(s_u, 68, p_w, msg_b1_0, n0, m0, lane, N);
}

// ---------------------------------------------------------------------------
// k_edge: 256 threads, 128 edges/block, warp-local.
// kt=0 B-fragments prefetched before the gather (overlaps idx->gather chain).
// ---------------------------------------------------------------------------
__global__ __launch_bounds__(256, 3) void k_edge(
    const int* __restrict__ src, const int* __restrict__ dst,
    int layer, const float* __restrict__ b2, int E)
{
    __shared__ uint s_u[128 * 36];
    __shared__ float s_b2[64];
    int tid = threadIdx.x;
    int e0 = blockIdx.x * 128;
    const uint* pw = p_w + layer * 12288 + 4096;   // msg w2 packed (K=64,N=64)

    if (tid < 64) s_b2[tid] = b2[tid];
    __syncthreads();   // the only block barrier

    int warp = tid >> 5, lane = tid & 31;
    int m0 = warp * 16;
    int qrow = lane >> 2, qcol = lane & 3;
    int lslot4 = (qcol * 8 + qrow) * 4;

    int sidx = -1, didx = -1;
    {
        int e = e0 + m0 + lane;
        if (lane < 16 && e < E) { sidx = src[e]; didx = dst[e]; }
    }

    // prefetch kt=0 B fragments (independent of edge data)
    uint4 Bp[4];
#pragma unroll
    for (int t = 0; t < 4; t++)
        Bp[t] = __ldg((const uint4*)(pw + t * 128 + lslot4));

    // gather + layer-1: 16 edges x 8 uint4 = 128 tasks / 32 lanes
#pragma unroll
    for (int i = 0; i < 4; i++) {
        int t = i * 32 + lane;
        int el = t >> 3, q = t & 7;
        int s = __shfl_sync(0xffffffffu, sidx, el);   // convergent
        int d = __shfl_sync(0xffffffffu, didx, el);   // convergent
        uint4 v = make_uint4(0u, 0u, 0u, 0u);
        if (s >= 0) {
            uint4 a = __ldg((const uint4*)(g_as + (size_t)s * 32 + q * 4));
            uint4 b = __ldg((const uint4*)(g_ad + (size_t)d * 32 + q * 4));
            v.x = brelu2(badd2(a.x, b.x));
            v.y = brelu2(badd2(a.y, b.y));
            v.z = brelu2(badd2(a.z, b.z));
            v.w = brelu2(badd2(a.w, b.w));
        }
        *(uint4*)(s_u + (m0 + el) * 36 + q * 4) = v;
    }
    __syncwarp();

    float acc[8][4];
#pragma unroll
    for (int nt = 0; nt < 8; nt++)
#pragma unroll
        for (int c = 0; c < 4; c++) acc[nt][c] = 0.f;

    uint sA = ldsm_base(s_u, 36, m0, lane);
    // kt = 0 with prefetched B: Bp[half*2 + c] holds {B0|B1}[c]
    {
        uint a0, a1, a2, a3;
        ldsm_x4(a0, a1, a2, a3, sA);
#pragma unroll
        for (int c = 0; c < 2; c++) {
            const uint* B0 = (const uint*)&Bp[c];          // half 0
            const uint* B1 = (const uint*)&Bp[2 + c];      // half 1
#pragma unroll
            for (int j = 0; j < 4; j++) {
                int nt = c * 4 + j;
                mma_bf16(acc[nt][0], acc[nt][1], acc[nt][2], acc[nt][3],
                         a0, a1, a2, a3, B0[j], B1[j]);
            }
        }
    }
#pragma unroll
    for (int kt = 1; kt < 4; kt++) {
        uint a0, a1, a2, a3;
        ldsm_x4(a0, a1, a2, a3, sA + kt * 32);
        const uint* p0 = pw + (kt * 2 + 0) * 256 + lslot4;
        const uint* p1 = pw + (kt * 2 + 1) * 256 + lslot4;
#pragma unroll
        for (int c = 0; c < 2; c++) {
            uint B0[4], B1[4];
            *(uint4*)&B0[0] = __ldg((const uint4*)(p0 + c * 128));
            *(uint4*)&B1[0] = __ldg((const uint4*)(p1 + c * 128));
#pragma unroll
            for (int j = 0; j < 4; j++) {
                int nt = c * 4 + j;
                mma_bf16(acc[nt][0], acc[nt][1], acc[nt][2], acc[nt][3],
                         a0, a1, a2, a3, B0[j], B1[j]);
            }
        }
    }
    __syncwarp();

    // epilogue: m = relu(acc + b2) -> own rows
#pragma unroll
    for (int nt = 0; nt < 8; nt++) {
        int c = nt * 8 + qcol * 2;
        float bx = s_b2[c], by = s_b2[c + 1];
        int cp = nt * 4 + qcol;
        s_u[(m0 + qrow) * 36 + cp] =
            bpack(fmaxf(acc[nt][0] + bx, 0.f), fmaxf(acc[nt][1] + by, 0.f));
        s_u[(m0 + qrow + 8) * 36 + cp] =
            bpack(fmaxf(acc[nt][2] + bx, 0.f), fmaxf(acc[nt][3] + by, 0.f));
    }
    __syncwarp();

    // scatter: 16 edges x 8 uint4 vector reds
#pragma unroll
    for (int i = 0; i < 4; i++) {
        int t = i * 32 + lane;
        int el = t >> 3, q = t & 7;
        int d = __shfl_sync(0xffffffffu, didx, el);   // convergent
        if (d >= 0) {
            uint4 v = *(const uint4*)(s_u + (m0 + el) * 36 + q * 4);
            red_v4_bf16(g_agg + (size_t)d * 32 + q * 4, v);
        }
    }
}

// ---------------------------------------------------------------------------
// k_upd: warp-local. h = mlp2(concat(h, agg/deg)); zeroes g_agg rows;
// if has_next: fused pre for layer+1; else: fused output head.
// Slab per row (stride 68 uints): [0,32) input / later h pairs, [32,64) hidden.
// ---------------------------------------------------------------------------
__global__ __launch_bounds__(256, 3) void k_upd(
    int layer, const float* __restrict__ b1, const float* __restrict__ b2,
    int has_next, const float* __restrict__ msg_b1_next,
    const float* __restrict__ ob1, const float* __restrict__ ow2,
    const float* __restrict__ ob2, float* __restrict__ outp, int N)
{
    __shared__ uint s_u[128 * 68];
    __shared__ float s_b1[64], s_b2[64];
    __shared__ float s_ob1[64], s_ow2[192], s_ob2[3];
    int tid = threadIdx.x;
    int n0 = blockIdx.x * 128;
    int is_last = !has_next;
    const uint* pw1 = p_w + layer * 12288 + 6144;
    const uint* pw2 = p_w + layer * 12288 + 10240;

    if (tid < 64) { s_b1[tid] = b1[tid]; s_b2[tid] = b2[tid]; }
    if (is_last) {
        if (tid >= 64 && tid < 128) s_ob1[tid - 64] = ob1[tid - 64];
        if (tid >= 128 && tid < 224) {
            s_ow2[tid - 128] = ow2[tid - 128];
            s_ow2[tid - 128 + 96] = ow2[tid - 128 + 96];
        }
        if (tid >= 224 && tid < 227) s_ob2[tid - 224] = ob2[tid - 224];
    }
    __syncthreads();

    int warp = tid >> 5, lane = tid & 31;
    int m0 = warp * 16;

    float ivreg = 1.f;
    if (lane < 16) {
        int n = n0 + m0 + lane;
        if (n < N) ivreg = 1.f / fmaxf(__ldg(g_cnt + n), 1.f);
    }

#pragma unroll
    for (int i = 0; i < 8; i++) {
        int t = i * 32 + lane;
        int rl = t >> 4, q = t & 15;
        float iv = __shfl_sync(0xffffffffu, ivreg, rl);   // convergent
        int n = n0 + m0 + rl;
        uint4 v = make_uint4(0u, 0u, 0u, 0u);
        if (n < N) {
            if (q < 8) {
                v = *(const uint4*)(g_hb + (size_t)n * 32 + q * 4);
            } else {
                int qq = q - 8;
                uint4 a = *(const uint4*)(g_agg + (size_t)n * 32 + qq * 4);
                float2 p0 = bunpack(a.x), p1 = bunpack(a.y);
                float2 p2 = bunpack(a.z), p3 = bunpack(a.w);
                v.x = bpack(p0.x * iv, p0.y * iv);
                v.y = bpack(p1.x * iv, p1.y * iv);
                v.z = bpack(p2.x * iv, p2.y * iv);
                v.w = bpack(p3.x * iv, p3.y * iv);
                *(uint4*)(g_agg + (size_t)n * 32 + qq * 4) = make_uint4(0u, 0u, 0u, 0u);
            }
        }
        *(uint4*)(s_u + (m0 + rl) * 68 + q * 4) = v;
    }
    __syncwarp();

    int qrow = lane >> 2, qcol = lane & 3;
    int lslot4 = (qcol * 8 + qrow) * 4;
    uint sA = ldsm_base(s_u, 68, m0, lane);

    // phase 1: K=128
    float acc[8][4];
#pragma unroll
    for (int nt = 0; nt < 8; nt++)
#pragma unroll
        for (int c = 0; c < 4; c++) acc[nt][c] = 0.f;
#pragma unroll
    for (int kt = 0; kt < 8; kt++) {
        uint a0, a1, a2, a3;
        ldsm_x4(a0, a1, a2, a3, sA + kt * 32);
        const uint* p0 = pw1 + (kt * 2 + 0) * 256 + lslot4;
        const uint* p1 = pw1 + (kt * 2 + 1) * 256 + lslot4;
#pragma unroll
        for (int c = 0; c < 2; c++) {
            uint B0[4], B1[4];
            *(uint4*)&B0[0] = __ldg((const uint4*)(p0 + c * 128));
            *(uint4*)&B1[0] = __ldg((const uint4*)(p1 + c * 128));
#pragma unroll
            for (int j = 0; j < 4; j++) {
                int nt = c * 4 + j;
                mma_bf16(acc[nt][0], acc[nt][1], acc[nt][2], acc[nt][3],
                         a0, a1, a2, a3, B0[j], B1[j]);
            }
        }
    }
    __syncwarp();

    // hidden -> slab offset 32
#pragma unroll
    for (int nt = 0; nt < 8; nt++) {
        int c = nt * 8 + qcol * 2;
        float bx = s_b1[c], by = s_b1[c + 1];
        int cp = 32 + nt * 4 + qcol;
        s_u[(m0 + qrow) * 68 + cp] =
            bpack(fmaxf(acc[nt][0] + bx, 0.f), fmaxf(acc[nt][1] + by, 0.f));
        s_u[(m0 + qrow + 8) * 68 + cp] =
            bpack(fmaxf(acc[nt][2] + bx, 0.f), fmaxf(acc[nt][3] + by, 0.f));
    }
    __syncwarp();

    // phase 2: K=64 (hidden at offset 32)
    float acc2[8][4];
#pragma unroll
    for (int nt = 0; nt < 8; nt++)
#pragma unroll
        for (int c = 0; c < 4; c++) acc2[nt][c] = 0.f;
#pragma unroll
    for (int kt = 0; kt < 4; kt++) {
        uint a0, a1, a2, a3;
        ldsm_x4(a0, a1, a2, a3, sA + 128 + kt * 32);
        const uint* p0 = pw2 + (kt * 2 + 0) * 256 + lslot4;
        const uint* p1 = pw2 + (kt * 2 + 1) * 256 + lslot4;
#pragma unroll
        for (int c = 0; c < 2; c++) {
            uint B0[4], B1[4];
            *(uint4*)&B0[0] = __ldg((const uint4*)(p0 + c * 128));
            *(uint4*)&B1[0] = __ldg((const uint4*)(p1 + c * 128));
#pragma unroll
            for (int j = 0; j < 4; j++) {
                int nt = c * 4 + j;
                mma_bf16(acc2[nt][0], acc2[nt][1], acc2[nt][2], acc2[nt][3],
                         a0, a1, a2, a3, B0[j], B1[j]);
            }
        }
    }
    __syncwarp();

    // h -> slab offset 0 + g_hb (if not last)
#pragma unroll
    for (int nt = 0; nt < 8; nt++) {
        int c = nt * 8 + qcol * 2;
        float bx = s_b2[c], by = s_b2[c + 1];
        int cp = nt * 4 + qcol;
        int nA = n0 + m0 + qrow;
        int nB = nA + 8;
        uint pA = bpack(fmaxf(acc2[nt][0] + bx, 0.f), fmaxf(acc2[nt][1] + by, 0.f));
        uint pB = bpack(fmaxf(acc2[nt][2] + bx, 0.f), fmaxf(acc2[nt][3] + by, 0.f));
        s_u[(m0 + qrow) * 68 + cp]     = pA;
        s_u[(m0 + qrow + 8) * 68 + cp] = pB;
        if (!is_last) {
            if (nA < N) g_hb[(size_t)nA * 32 + cp] = pA;
            if (nB < N) g_hb[(size_t)nB * 32 + cp] = pB;
        }
    }
    __syncwarp();

    if (has_next) {
        pre_mma(s_u, 68, p_w + (layer + 1) * 12288, msg_b1_next,
                n0, m0, lane, N);
        return;
    }

    // ---- fused output head ----
    const uint* pw3 = p_w + 3 * 12288;
    float acc3[8][4];
#pragma unroll
    for (int nt = 0; nt < 8; nt++)
#pragma unroll
        for (int c = 0; c < 4; c++) acc3[nt][c] = 0.f;
#pragma unroll
    for (int kt = 0; kt < 4; kt++) {
        uint a0, a1, a2, a3;
        ldsm_x4(a0, a1, a2, a3, sA + kt * 32);
        const uint* p0 = pw3 + (kt * 2 + 0) * 256 + lslot4;
        const uint* p1 = pw3 + (kt * 2 + 1) * 256 + lslot4;
#pragma unroll
        for (int c = 0; c < 2; c++) {
            uint B0[4], B1[4];
            *(uint4*)&B0[0] = __ldg((const uint4*)(p0 + c * 128));
            *(uint4*)&B1[0] = __ldg((const uint4*)(p1 + c * 128));
#pragma unroll
            for (int j = 0; j < 4; j++) {
                int nt = c * 4 + j;
                mma_bf16(acc3[nt][0], acc3[nt][1], acc3[nt][2], acc3[nt][3],
                         a0, a1, a2, a3, B0[j], B1[j]);
            }
        }
    }

    float pA[3] = {0.f, 0.f, 0.f}, pB[3] = {0.f, 0.f, 0.f};
#pragma unroll
    for (int nt = 0; nt < 8; nt++) {
        int c = nt * 8 + qcol * 2;
        float o1a = s_ob1[c], o1b = s_ob1[c + 1];
        float hA0 = fmaxf(acc3[nt][0] + o1a, 0.f);
        float hA1 = fmaxf(acc3[nt][1] + o1b, 0.f);
        float hB0 = fmaxf(acc3[nt][2] + o1a, 0.f);
        float hB1 = fmaxf(acc3[nt][3] + o1b, 0.f);
#pragma unroll
        for (int cc = 0; cc < 3; cc++) {
            float w0 = s_ow2[c * 3 + cc], w1v = s_ow2[(c + 1) * 3 + cc];
            pA[cc] = fmaf(hA0, w0, fmaf(hA1, w1v, pA[cc]));
            pB[cc] = fmaf(hB0, w0, fmaf(hB1, w1v, pB[cc]));
        }
    }
#pragma unroll
    for (int cc = 0; cc < 3; cc++) {
        pA[cc] += __shfl_xor_sync(0xffffffffu, pA[cc], 1);
        pA[cc] += __shfl_xor_sync(0xffffffffu, pA[cc], 2);
        pB[cc] += __shfl_xor_sync(0xffffffffu, pB[cc], 1);
        pB[cc] += __shfl_xor_sync(0xffffffffu, pB[cc], 2);
    }
    if (qcol == 0) {
        int nA = n0 + m0 + qrow;
        int nB = nA + 8;
        if (nA < N) {
#pragma unroll
            for (int cc = 0; cc < 3; cc++)
                outp[(size_t)nA * 3 + cc] =
                    6.283185307179586f / (1.f + expf(-(pA[cc] + s_ob2[cc])));
        }
        if (nB < N) {
#pragma unroll
            for (int cc = 0; cc < 3; cc++)
                outp[(size_t)nB * 3 + cc] =
                    6.283185307179586f / (1.f + expf(-(pB[cc] + s_ob2[cc])));
        }
    }
}

// ---------------------------------------------------------------------------
extern "C" void kernel_launch(void* const* d_in, const int* in_sizes, int n_in,
                              void* d_out, int out_size)
{
    const float* x      = (const float*)d_in[0];
    const int*   ei     = (const int*)  d_in[1];
    const float* enc_w1 = (const float*)d_in[2];
    const float* enc_b1 = (const float*)d_in[3];
    const float* enc_w2 = (const float*)d_in[4];
    const float* enc_b2 = (const float*)d_in[5];
    const float* msg_w1 = (const float*)d_in[6];
    const float* msg_b1 = (const float*)d_in[7];
    const float* msg_w2 = (const float*)d_in[8];
    const float* msg_b2 = (const float*)d_in[9];
    const float* upd_w1 = (const float*)d_in[10];
    const float* upd_b1 = (const float*)d_in[11];
    const float* upd_w2 = (const float*)d_in[12];
    const float* upd_b2 = (const float*)d_in[13];
    const float* out_w1 = (const float*)d_in[14];
    const float* out_b1 = (const float*)d_in[15];
    const float* out_w2 = (const float*)d_in[16];
    const float* out_b2 = (const float*)d_in[17];

    int N = in_sizes[0] / 5;
    int E = in_sizes[1] / 2;
    if (N > NMAX) N = NMAX;
    if (E > EMAX) E = EMAX;
    const int* src = ei;
    const int* dstp = ei + E;

    int nbE256 = (E + 255) / 256;
    int nbN128 = (N + 127) / 128;
    int nbE128 = (E + 127) / 128;

    k_pack<<<(PACKN + N + 255) / 256, 256>>>(msg_w1, msg_w2, upd_w1, upd_w2,
                                             out_w1, enc_w2, N);
    k_count<<<nbE256, 256>>>(dstp, E);
    k_encoder<<<nbN128, 256>>>(x, enc_w1, enc_b1, enc_b2, msg_b1, N);

    for (int l = 0; l < 3; l++) {
        k_edge<<<nbE128, 256>>>(src, dstp, l, msg_b2 + l * 64, E);
        k_upd<<<nbN128, 256>>>(l, upd_b1 + l * 64, upd_b2 + l * 64,
                               (l < 2) ? 1 : 0, msg_b1 + (l + 1) * 64,
                               out_b1, out_w2, out_b2, (float*)d_out, N);
    }
}

// round 17
// speedup vs baseline: 1.1052x; 1.0174x over previous
#include <cuda_runtime.h>
#include <cuda_bf16.h>

// ---------------------------------------------------------------------------
// FixedSimpleGNN: 3-layer MPNN, N=100000, E=1000000, H=64.
//   - per-node a_s/a_d (factorized msg layer-1, bias folded into a_s)
//   - per-edge bf16 mma.m16n8k16 msg layer-2, warp-local
//   - v4.bf16x2 red scatter
//   - warp-local bf16 mma update MLP; output head fused into last update
//   - encoder layer-2 on tensor cores (packed enc_w2), fused pre-phase
//   - k_edge in its best-measured R14 form (launch_bounds(256,4), no prefetch)
// ---------------------------------------------------------------------------

#define NMAX 100000
#define EMAX 1000000
#define PACKN (3 * 12288 + 4096)

typedef unsigned int uint;

__device__ uint  g_hb [NMAX * 32];   // h, bf16x2 pairs
__device__ uint  g_as [NMAX * 32];   // bf16x2 pairs (msg_b1 folded in)
__device__ uint  g_ad [NMAX * 32];   // bf16x2 pairs
__device__ uint  g_agg[NMAX * 32];   // bf16x2 pairs (atomic accum)
__device__ float g_cnt[NMAX];

// packed bf16x2 weights, warp-coalesced B-fragment layout (see k_pack):
//   per layer l*12288: +0 msg W' (N=128) | +4096 msg w2 | +6144 upd w1 | +10240 upd w2
//   +36864 out w1 | +38912 enc w2
__device__ uint p_w[PACKN];

__device__ __forceinline__ uint bpack(float lo, float hi) {
    __nv_bfloat162 p = __floats2bfloat162_rn(lo, hi);
    return *(uint*)&p;
}
__device__ __forceinline__ float2 bunpack(uint v) {
    return __bfloat1622float2(*(__nv_bfloat162*)&v);
}
__device__ __forceinline__ uint badd2(uint a, uint b) {
    __nv_bfloat162 r = __hadd2(*(__nv_bfloat162*)&a, *(__nv_bfloat162*)&b);
    return *(uint*)&r;
}
__device__ __forceinline__ uint brelu2(uint a) {
    __nv_bfloat162 z = __float2bfloat162_rn(0.f);
    __nv_bfloat162 r = __hmax2(*(__nv_bfloat162*)&a, z);
    return *(uint*)&r;
}
__device__ __forceinline__ void mma_bf16(
    float& c0, float& c1, float& c2, float& c3,
    uint a0, uint a1, uint a2, uint a3, uint b0, uint b1)
{
    asm volatile(
        "mma.sync.aligned.m16n8k16.row.col.f32.bf16.bf16.f32 "
        "{%0,%1,%2,%3}, {%4,%5,%6,%7}, {%8,%9}, {%0,%1,%2,%3};"
        : "+f"(c0), "+f"(c1), "+f"(c2), "+f"(c3)
        : "r"(a0), "r"(a1), "r"(a2), "r"(a3), "r"(b0), "r"(b1));
}
__device__ __forceinline__ void red_v4_bf16(uint* addr, uint4 v) {
    asm volatile(
        "red.global.add.noftz.v4.bf16x2 [%0], {%1,%2,%3,%4};"
        :: "l"(addr), "r"(v.x), "r"(v.y), "r"(v.z), "r"(v.w) : "memory");
}
__device__ __forceinline__ void ldsm_x4(
    uint& a0, uint& a1, uint& a2, uint& a3, uint saddr)
{
    asm volatile(
        "ldmatrix.sync.aligned.m8n8.x4.shared.b16 {%0,%1,%2,%3}, [%4];"
        : "=r"(a0), "=r"(a1), "=r"(a2), "=r"(a3) : "r"(saddr));
}
__device__ __forceinline__ uint ldsm_base(const uint* s_u, int stride,
                                          int m0, int lane)
{
    const uint* p = s_u + (m0 + (lane & 15)) * stride + ((lane & 16) >> 2);
    return (uint)__cvta_generic_to_shared(p);
}

// ---------------------------------------------------------------------------
// k_pack: build warp-coalesced bf16x2 weight arrays; also zeroes g_cnt.
// ---------------------------------------------------------------------------
__global__ void k_pack(const float* __restrict__ msg_w1,
                       const float* __restrict__ msg_w2,
                       const float* __restrict__ upd_w1,
                       const float* __restrict__ upd_w2,
                       const float* __restrict__ out_w1,
                       const float* __restrict__ enc_w2, int N)
{
    int idx = blockIdx.x * blockDim.x + threadIdx.x;
    if (idx >= PACKN) {
        int i = idx - PACKN;
        if (i < N) g_cnt[i] = 0.f;
        return;
    }
    const float* W;
    int r;
    bool wide = false;
    if (idx >= 3 * 12288 + 2048) {
        r = idx - (3 * 12288 + 2048); W = enc_w2;
    } else if (idx >= 3 * 12288) {
        r = idx - 3 * 12288; W = out_w1;
    } else {
        int l = idx / 12288; r = idx % 12288;
        if (r < 4096)       { W = msg_w1 + l * 8192; wide = true; }
        else if (r < 6144)  { r -= 4096;  W = msg_w2 + l * 4096; }
        else if (r < 10240) { r -= 6144;  W = upd_w1 + l * 8192; }
        else                { r -= 10240; W = upd_w2 + l * 4096; }
    }
    int j = r & 3;
    int slot = (r >> 2) & 31;
    int qr = slot & 7, qc = slot >> 3;
    int c, half, kt;
    if (wide) { c = (r >> 7) & 3; half = (r >> 9) & 1; kt = r >> 10; }
    else      { c = (r >> 7) & 1; half = (r >> 8) & 1; kt = r >> 9; }
    int kp = kt * 8 + half * 4 + qc;
    int n = (c * 4 + j) * 8 + qr;
    float lo, hi;
    if (wide && n >= 64) {
        lo = W[(64 + 2*kp) * 64 + (n - 64)];
        hi = W[(64 + 2*kp + 1) * 64 + (n - 64)];
    } else {
        lo = W[(2*kp) * 64 + n];
        hi = W[(2*kp + 1) * 64 + n];
    }
    p_w[idx] = bpack(lo, hi);
}

// ---------------------------------------------------------------------------
__global__ void k_count(const int* __restrict__ dst, int E) {
    int e = blockIdx.x * blockDim.x + threadIdx.x;
    if (e < E) atomicAdd(&g_cnt[dst[e]], 1.f);
}

// ---------------------------------------------------------------------------
// pre-phase mma: A = bf16 h pairs in s_u (offset 0, given stride),
// B = W' (K=64, N=128) packed. Warp covers rows m0..m0+15, 128 cols.
// msg_b1 of the target layer is folded into the a_s half.
// ---------------------------------------------------------------------------
__device__ __forceinline__ void pre_mma(
    const uint* s_u, int stride, const uint* pw, const float* __restrict__ b1g,
    int n0, int m0, int lane, int N)
{
    int qrow = lane >> 2, qcol = lane & 3;
    int lslot4 = (qcol * 8 + qrow) * 4;

    float acc[16][4];
#pragma unroll
    for (int nt = 0; nt < 16; nt++)
#pragma unroll
        for (int c = 0; c < 4; c++) acc[nt][c] = 0.f;

    uint sA = ldsm_base(s_u, stride, m0, lane);
#pragma unroll
    for (int kt = 0; kt < 4; kt++) {
        uint a0, a1, a2, a3;
        ldsm_x4(a0, a1, a2, a3, sA + kt * 32);
        const uint* p0 = pw + (kt * 2 + 0) * 512 + lslot4;
        const uint* p1 = pw + (kt * 2 + 1) * 512 + lslot4;
#pragma unroll
        for (int c = 0; c < 4; c++) {
            uint B0[4], B1[4];
            *(uint4*)&B0[0] = __ldg((const uint4*)(p0 + c * 128));
            *(uint4*)&B1[0] = __ldg((const uint4*)(p1 + c * 128));
#pragma unroll
            for (int j = 0; j < 4; j++) {
                int nt = c * 4 + j;
                mma_bf16(acc[nt][0], acc[nt][1], acc[nt][2], acc[nt][3],
                         a0, a1, a2, a3, B0[j], B1[j]);
            }
        }
    }
#pragma unroll
    for (int nt = 0; nt < 16; nt++) {
        int col = nt * 8 + qcol * 2;
        int nA = n0 + m0 + qrow;
        int nB = nA + 8;
        if (col < 64) {
            float bx = __ldg(b1g + col), by = __ldg(b1g + col + 1);
            if (nA < N) g_as[(size_t)nA * 32 + (col >> 1)] =
                bpack(acc[nt][0] + bx, acc[nt][1] + by);
            if (nB < N) g_as[(size_t)nB * 32 + (col >> 1)] =
                bpack(acc[nt][2] + bx, acc[nt][3] + by);
        } else {
            int cp = (col - 64) >> 1;
            if (nA < N) g_ad[(size_t)nA * 32 + cp] = bpack(acc[nt][0], acc[nt][1]);
            if (nB < N) g_ad[(size_t)nB * 32 + cp] = bpack(acc[nt][2], acc[nt][3]);
        }
    }
}

// ---------------------------------------------------------------------------
// encoder (mma version): layer1 scalar (K=5) -> bf16 hidden (slab offset 32),
// layer2 via packed enc_w2 mma -> h (slab offset 0 + g_hb), fused pre_mma.
// Slab: 128 rows x 68 uints. Zeroes g_agg.
// ---------------------------------------------------------------------------
__global__ __launch_bounds__(256) void k_encoder(
    const float* __restrict__ x,
    const float* __restrict__ w1, const float* __restrict__ b1,
    const float* __restrict__ b2,
    const float* __restrict__ msg_b1_0, int N)
{
    __shared__ uint s_u[128 * 68];
    __shared__ float s_w1[5 * 64], s_b1[64], s_b2[64];
    int tid = threadIdx.x;
    int n0 = blockIdx.x * 128;

    for (int i = tid; i < 5 * 64; i += 256) s_w1[i] = w1[i];
    if (tid < 64) { s_b1[tid] = b1[tid]; s_b2[tid] = b2[tid]; }
#pragma unroll
    for (int i = 0; i < 4; i++) {
        int lin = i * 256 + tid;
        int r = lin >> 3, q = lin & 7;
        int n = n0 + r;
        if (n < N)
            *(uint4*)(g_agg + (size_t)n * 32 + q * 4) = make_uint4(0u, 0u, 0u, 0u);
    }
    __syncthreads();

    // layer 1: thread handles row (tid & 127), cols half*32..+32
    {
        int row = tid & 127, half = tid >> 7;
        int n = n0 + row;
        float xv[5];
#pragma unroll
        for (int k = 0; k < 5; k++)
            xv[k] = (n < N) ? __ldg(x + (size_t)n * 5 + k) : 0.f;
#pragma unroll
        for (int j = 0; j < 32; j += 2) {
            int c = half * 32 + j;
            float v0 = s_b1[c], v1 = s_b1[c + 1];
#pragma unroll
            for (int k = 0; k < 5; k++) {
                v0 = fmaf(xv[k], s_w1[k * 64 + c], v0);
                v1 = fmaf(xv[k], s_w1[k * 64 + c + 1], v1);
            }
            s_u[row * 68 + 32 + (c >> 1)] =
                bpack(fmaxf(v0, 0.f), fmaxf(v1, 0.f));
        }
    }
    __syncthreads();

    int warp = tid >> 5, lane = tid & 31;
    int m0 = warp * 16;
    int qrow = lane >> 2, qcol = lane & 3;
    int lslot4 = (qcol * 8 + qrow) * 4;
    uint sA = ldsm_base(s_u, 68, m0, lane);
    const uint* pw2 = p_w + 3 * 12288 + 2048;   // enc w2 packed (K=64,N=64)

    // layer 2: K=64 (hidden at offset 32)
    float acc[8][4];
#pragma unroll
    for (int nt = 0; nt < 8; nt++)
#pragma unroll
        for (int c = 0; c < 4; c++) acc[nt][c] = 0.f;
#pragma unroll
    for (int kt = 0; kt < 4; kt++) {
        uint a0, a1, a2, a3;
        ldsm_x4(a0, a1, a2, a3, sA + 128 + kt * 32);
        const uint* p0 = pw2 + (kt * 2 + 0) * 256 + lslot4;
        const uint* p1 = pw2 + (kt * 2 + 1) * 256 + lslot4;
#pragma unroll
        for (int c = 0; c < 2; c++) {
            uint B0[4], B1[4];
            *(uint4*)&B0[0] = __ldg((const uint4*)(p0 + c * 128));
            *(uint4*)&B1[0] = __ldg((const uint4*)(p1 + c * 128));
#pragma unroll
            for (int j = 0; j < 4; j++) {
                int nt = c * 4 + j;
                mma_bf16(acc[nt][0], acc[nt][1], acc[nt][2], acc[nt][3],
                         a0, a1, a2, a3, B0[j], B1[j]);
            }
        }
    }
    __syncwarp();

    // h = relu(acc + b2) -> slab offset 0 + g_hb
#pragma unroll
    for (int nt = 0; nt < 8; nt++) {
        int c = nt * 8 + qcol * 2;
        float bx = s_b2[c], by = s_b2[c + 1];
        int cp = nt * 4 + qcol;
        int nA = n0 + m0 + qrow;
        int nB = nA + 8;
        uint pA = bpack(fmaxf(acc[nt][0] + bx, 0.f), fmaxf(acc[nt][1] + by, 0.f));
        uint pB = bpack(fmaxf(acc[nt][2] + bx, 0.f), fmaxf(acc[nt][3] + by, 0.f));
        s_u[(m0 + qrow) * 68 + cp]     = pA;
        s_u[(m0 + qrow + 8) * 68 + cp] = pB;
        if (nA < N) g_hb[(size_t)nA * 32 + cp] = pA;
        if (nB < N) g_hb[(size_t)nB * 32 + cp] = pB;
    }
    __syncwarp();

    pre_mma(s_u, 68, p_w, msg_b1_0, n0, m0, lane, N);
}

// ---------------------------------------------------------------------------
// k_edge (R14 best form): 256 threads, 128 edges/block, warp-local, 4 blk/SM.
// ---------------------------------------------------------------------------
__global__ __launch_bounds__(256, 4) void k_edge(
    const int* __restrict__ src, const int* __restrict__ dst,
    int layer, const float* __restrict__ b2, int E)
{
    __shared__ uint s_u[128 * 36];
    __shared__ float s_b2[64];
    int tid = threadIdx.x;
    int e0 = blockIdx.x * 128;
    const uint* pw = p_w + layer * 12288 + 4096;   // msg w2 packed (K=64,N=64)

    if (tid < 64) s_b2[tid] = b2[tid];
    __syncthreads();   // the only block barrier

    int warp = tid >> 5, lane = tid & 31;
    int m0 = warp * 16;

    int sidx = -1, didx = -1;
    {
        int e = e0 + m0 + lane;
        if (lane < 16 && e < E) { sidx = src[e]; didx = dst[e]; }
    }

    // gather + layer-1: 16 edges x 8 uint4 = 128 tasks / 32 lanes
#pragma unroll
    for (int i = 0; i < 4; i++) {
        int t = i * 32 + lane;
        int el = t >> 3, q = t & 7;
        int s = __shfl_sync(0xffffffffu, sidx, el);   // convergent
        int d = __shfl_sync(0xffffffffu, didx, el);   // convergent
        uint4 v = make_uint4(0u, 0u, 0u, 0u);
        if (s >= 0) {
            uint4 a = __ldg((const uint4*)(g_as + (size_t)s * 32 + q * 4));
            uint4 b = __ldg((const uint4*)(g_ad + (size_t)d * 32 + q * 4));
            v.x = brelu2(badd2(a.x, b.x));
            v.y = brelu2(badd2(a.y, b.y));
            v.z = brelu2(badd2(a.z, b.z));
            v.w = brelu2(badd2(a.w, b.w));
        }
        *(uint4*)(s_u + (m0 + el) * 36 + q * 4) = v;
    }
    __syncwarp();

    int qrow = lane >> 2, qcol = lane & 3;
    int lslot4 = (qcol * 8 + qrow) * 4;

    float acc[8][4];
#pragma unroll
    for (int nt = 0; nt < 8; nt++)
#pragma unroll
        for (int c = 0; c < 4; c++) acc[nt][c] = 0.f;

    uint sA = ldsm_base(s_u, 36, m0, lane);
#pragma unroll
    for (int kt = 0; kt < 4; kt++) {
        uint a0, a1, a2, a3;
        ldsm_x4(a0, a1, a2, a3, sA + kt * 32);
        const uint* p0 = pw + (kt * 2 + 0) * 256 + lslot4;
        const uint* p1 = pw + (kt * 2 + 1) * 256 + lslot4;
#pragma unroll
        for (int c = 0; c < 2; c++) {
            uint B0[4], B1[4];
            *(uint4*)&B0[0] = __ldg((const uint4*)(p0 + c * 128));
            *(uint4*)&B1[0] = __ldg((const uint4*)(p1 + c * 128));
#pragma unroll
            for (int j = 0; j < 4; j++) {
                int nt = c * 4 + j;
                mma_bf16(acc[nt][0], acc[nt][1], acc[nt][2], acc[nt][3],
                         a0, a1, a2, a3, B0[j], B1[j]);
            }
        }
    }
    __syncwarp();

    // epilogue: m = relu(acc + b2) -> own rows
#pragma unroll
    for (int nt = 0; nt < 8; nt++) {
        int c = nt * 8 + qcol * 2;
        float bx = s_b2[c], by = s_b2[c + 1];
        int cp = nt * 4 + qcol;
        s_u[(m0 + qrow) * 36 + cp] =
            bpack(fmaxf(acc[nt][0] + bx, 0.f), fmaxf(acc[nt][1] + by, 0.f));
        s_u[(m0 + qrow + 8) * 36 + cp] =
            bpack(fmaxf(acc[nt][2] + bx, 0.f), fmaxf(acc[nt][3] + by, 0.f));
    }
    __syncwarp();

    // scatter: 16 edges x 8 uint4 vector reds
#pragma unroll
    for (int i = 0; i < 4; i++) {
        int t = i * 32 + lane;
        int el = t >> 3, q = t & 7;
        int d = __shfl_sync(0xffffffffu, didx, el);   // convergent
        if (d >= 0) {
            uint4 v = *(const uint4*)(s_u + (m0 + el) * 36 + q * 4);
            red_v4_bf16(g_agg + (size_t)d * 32 + q * 4, v);
        }
    }
}

// ---------------------------------------------------------------------------
// k_upd: warp-local. h = mlp2(concat(h, agg/deg)); zeroes g_agg rows;
// if has_next: fused pre for layer+1; else: fused output head.
// Slab per row (stride 68 uints): [0,32) input / later h pairs, [32,64) hidden.
// ---------------------------------------------------------------------------
__global__ __launch_bounds__(256, 3) void k_upd(
    int layer, const float* __restrict__ b1, const float* __restrict__ b2,
    int has_next, const float* __restrict__ msg_b1_next,
    const float* __restrict__ ob1, const float* __restrict__ ow2,
    const float* __restrict__ ob2, float* __restrict__ outp, int N)
{
    __shared__ uint s_u[128 * 68];
    __shared__ float s_b1[64], s_b2[64];
    __shared__ float s_ob1[64], s_ow2[192], s_ob2[3];
    int tid = threadIdx.x;
    int n0 = blockIdx.x * 128;
    int is_last = !has_next;
    const uint* pw1 = p_w + layer * 12288 + 6144;
    const uint* pw2 = p_w + layer * 12288 + 10240;

    if (tid < 64) { s_b1[tid] = b1[tid]; s_b2[tid] = b2[tid]; }
    if (is_last) {
        if (tid >= 64 && tid < 128) s_ob1[tid - 64] = ob1[tid - 64];
        if (tid >= 128 && tid < 224) {
            s_ow2[tid - 128] = ow2[tid - 128];
            s_ow2[tid - 128 + 96] = ow2[tid - 128 + 96];
        }
        if (tid >= 224 && tid < 227) s_ob2[tid - 224] = ob2[tid - 224];
    }
    __syncthreads();

    int warp = tid >> 5, lane = tid & 31;
    int m0 = warp * 16;

    float ivreg = 1.f;
    if (lane < 16) {
        int n = n0 + m0 + lane;
        if (n < N) ivreg = 1.f / fmaxf(__ldg(g_cnt + n), 1.f);
    }

#pragma unroll
    for (int i = 0; i < 8; i++) {
        int t = i * 32 + lane;
        int rl = t >> 4, q = t & 15;
        float iv = __shfl_sync(0xffffffffu, ivreg, rl);   // convergent
        int n = n0 + m0 + rl;
        uint4 v = make_uint4(0u, 0u, 0u, 0u);
        if (n < N) {
            if (q < 8) {
                v = *(const uint4*)(g_hb + (size_t)n * 32 + q * 4);
            } else {
                int qq = q - 8;
                uint4 a = *(const uint4*)(g_agg + (size_t)n * 32 + qq * 4);
                float2 p0 = bunpack(a.x), p1 = bunpack(a.y);
                float2 p2 = bunpack(a.z), p3 = bunpack(a.w);
                v.x = bpack(p0.x * iv, p0.y * iv);
                v.y = bpack(p1.x * iv, p1.y * iv);
                v.z = bpack(p2.x * iv, p2.y * iv);
                v.w = bpack(p3.x * iv, p3.y * iv);
                *(uint4*)(g_agg + (size_t)n * 32 + qq * 4) = make_uint4(0u, 0u, 0u, 0u);
            }
        }
        *(uint4*)(s_u + (m0 + rl) * 68 + q * 4) = v;
    }
    __syncwarp();

    int qrow = lane >> 2, qcol = lane & 3;
    int lslot4 = (qcol * 8 + qrow) * 4;
    uint sA = ldsm_base(s_u, 68, m0, lane);

    // phase 1: K=128
    float acc[8][4];
#pragma unroll
    for (int nt = 0; nt < 8; nt++)
#pragma unroll
        for (int c = 0; c < 4; c++) acc[nt][c] = 0.f;
#pragma unroll
    for (int kt = 0; kt < 8; kt++) {
        uint a0, a1, a2, a3;
        ldsm_x4(a0, a1, a2, a3, sA + kt * 32);
        const uint* p0 = pw1 + (kt * 2 + 0) * 256 + lslot4;
        const uint* p1 = pw1 + (kt * 2 + 1) * 256 + lslot4;
#pragma unroll
        for (int c = 0; c < 2; c++) {
            uint B0[4], B1[4];
            *(uint4*)&B0[0] = __ldg((const uint4*)(p0 + c * 128));
            *(uint4*)&B1[0] = __ldg((const uint4*)(p1 + c * 128));
#pragma unroll
            for (int j = 0; j < 4; j++) {
                int nt = c * 4 + j;
                mma_bf16(acc[nt][0], acc[nt][1], acc[nt][2], acc[nt][3],
                         a0, a1, a2, a3, B0[j], B1[j]);
            }
        }
    }
    __syncwarp();

    // hidden -> slab offset 32
#pragma unroll
    for (int nt = 0; nt < 8; nt++) {
        int c = nt * 8 + qcol * 2;
        float bx = s_b1[c], by = s_b1[c + 1];
        int cp = 32 + nt * 4 + qcol;
        s_u[(m0 + qrow) * 68 + cp] =
            bpack(fmaxf(acc[nt][0] + bx, 0.f), fmaxf(acc[nt][1] + by, 0.f));
        s_u[(m0 + qrow + 8) * 68 + cp] =
            bpack(fmaxf(acc[nt][2] + bx, 0.f), fmaxf(acc[nt][3] + by, 0.f));
    }
    __syncwarp();

    // phase 2: K=64 (hidden at offset 32)
    float acc2[8][4];
#pragma unroll
    for (int nt = 0; nt < 8; nt++)
#pragma unroll
        for (int c = 0; c < 4; c++) acc2[nt][c] = 0.f;
#pragma unroll
    for (int kt = 0; kt < 4; kt++) {
        uint a0, a1, a2, a3;
        ldsm_x4(a0, a1, a2, a3, sA + 128 + kt * 32);
        const uint* p0 = pw2 + (kt * 2 + 0) * 256 + lslot4;
        const uint* p1 = pw2 + (kt * 2 + 1) * 256 + lslot4;
#pragma unroll
        for (int c = 0; c < 2; c++) {
            uint B0[4], B1[4];
            *(uint4*)&B0[0] = __ldg((const uint4*)(p0 + c * 128));
            *(uint4*)&B1[0] = __ldg((const uint4*)(p1 + c * 128));
#pragma unroll
            for (int j = 0; j < 4; j++) {
                int nt = c * 4 + j;
                mma_bf16(acc2[nt][0], acc2[nt][1], acc2[nt][2], acc2[nt][3],
                         a0, a1, a2, a3, B0[j], B1[j]);
            }
        }
    }
    __syncwarp();

    // h -> slab offset 0 + g_hb (if not last)
#pragma unroll
    for (int nt = 0; nt < 8; nt++) {
        int c = nt * 8 + qcol * 2;
        float bx = s_b2[c], by = s_b2[c + 1];
        int cp = nt * 4 + qcol;
        int nA = n0 + m0 + qrow;
        int nB = nA + 8;
        uint pA = bpack(fmaxf(acc2[nt][0] + bx, 0.f), fmaxf(acc2[nt][1] + by, 0.f));
        uint pB = bpack(fmaxf(acc2[nt][2] + bx, 0.f), fmaxf(acc2[nt][3] + by, 0.f));
        s_u[(m0 + qrow) * 68 + cp]     = pA;
        s_u[(m0 + qrow + 8) * 68 + cp] = pB;
        if (!is_last) {
            if (nA < N) g_hb[(size_t)nA * 32 + cp] = pA;
            if (nB < N) g_hb[(size_t)nB * 32 + cp] = pB;
        }
    }
    __syncwarp();

    if (has_next) {
        pre_mma(s_u, 68, p_w + (layer + 1) * 12288, msg_b1_next,
                n0, m0, lane, N);
        return;
    }

    // ---- fused output head ----
    const uint* pw3 = p_w + 3 * 12288;
    float acc3[8][4];
#pragma unroll
    for (int nt = 0; nt < 8; nt++)
#pragma unroll
        for (int c = 0; c < 4; c++) acc3[nt][c] = 0.f;
#pragma unroll
    for (int kt = 0; kt < 4; kt++) {
        uint a0, a1, a2, a3;
        ldsm_x4(a0, a1, a2, a3, sA + kt * 32);
        const uint* p0 = pw3 + (kt * 2 + 0) * 256 + lslot4;
        const uint* p1 = pw3 + (kt * 2 + 1) * 256 + lslot4;
#pragma unroll
        for (int c = 0; c < 2; c++) {
            uint B0[4], B1[4];
            *(uint4*)&B0[0] = __ldg((const uint4*)(p0 + c * 128));
            *(uint4*)&B1[0] = __ldg((const uint4*)(p1 + c * 128));
#pragma unroll
            for (int j = 0; j < 4; j++) {
                int nt = c * 4 + j;
                mma_bf16(acc3[nt][0], acc3[nt][1], acc3[nt][2], acc3[nt][3],
                         a0, a1, a2, a3, B0[j], B1[j]);
            }
        }
    }

    float pA[3] = {0.f, 0.f, 0.f}, pB[3] = {0.f, 0.f, 0.f};
#pragma unroll
    for (int nt = 0; nt < 8; nt++) {
        int c = nt * 8 + qcol * 2;
        float o1a = s_ob1[c], o1b = s_ob1[c + 1];
        float hA0 = fmaxf(acc3[nt][0] + o1a, 0.f);
        float hA1 = fmaxf(acc3[nt][1] + o1b, 0.f);
        float hB0 = fmaxf(acc3[nt][2] + o1a, 0.f);
        float hB1 = fmaxf(acc3[nt][3] + o1b, 0.f);
#pragma unroll
        for (int cc = 0; cc < 3; cc++) {
            float w0 = s_ow2[c * 3 + cc], w1v = s_ow2[(c + 1) * 3 + cc];
            pA[cc] = fmaf(hA0, w0, fmaf(hA1, w1v, pA[cc]));
            pB[cc] = fmaf(hB0, w0, fmaf(hB1, w1v, pB[cc]));
        }
    }
#pragma unroll
    for (int cc = 0; cc < 3; cc++) {
        pA[cc] += __shfl_xor_sync(0xffffffffu, pA[cc], 1);
        pA[cc] += __shfl_xor_sync(0xffffffffu, pA[cc], 2);
        pB[cc] += __shfl_xor_sync(0xffffffffu, pB[cc], 1);
        pB[cc] += __shfl_xor_sync(0xffffffffu, pB[cc], 2);
    }
    if (qcol == 0) {
        int nA = n0 + m0 + qrow;
        int nB = nA + 8;
        if (nA < N) {
#pragma unroll
            for (int cc = 0; cc < 3; cc++)
                outp[(size_t)nA * 3 + cc] =
                    6.283185307179586f / (1.f + expf(-(pA[cc] + s_ob2[cc])));
        }
        if (nB < N) {
#pragma unroll
            for (int cc = 0; cc < 3; cc++)
                outp[(size_t)nB * 3 + cc] =
                    6.283185307179586f / (1.f + expf(-(pB[cc] + s_ob2[cc])));
        }
    }
}

// ---------------------------------------------------------------------------
extern "C" void kernel_launch(void* const* d_in, const int* in_sizes, int n_in,
                              void* d_out, int out_size)
{
    const float* x      = (const float*)d_in[0];
    const int*   ei     = (const int*)  d_in[1];
    const float* enc_w1 = (const float*)d_in[2];
    const float* enc_b1 = (const float*)d_in[3];
    const float* enc_w2 = (const float*)d_in[4];
    const float* enc_b2 = (const float*)d_in[5];
    const float* msg_w1 = (const float*)d_in[6];
    const float* msg_b1 = (const float*)d_in[7];
    const float* msg_w2 = (const float*)d_in[8];
    const float* msg_b2 = (const float*)d_in[9];
    const float* upd_w1 = (const float*)d_in[10];
    const float* upd_b1 = (const float*)d_in[11];
    const float* upd_w2 = (const float*)d_in[12];
    const float* upd_b2 = (const float*)d_in[13];
    const float* out_w1 = (const float*)d_in[14];
    const float* out_b1 = (const float*)d_in[15];
    const float* out_w2 = (const float*)d_in[16];
    const float* out_b2 = (const float*)d_in[17];

    int N = in_sizes[0] / 5;
    int E = in_sizes[1] / 2;
    if (N > NMAX) N = NMAX;
    if (E > EMAX) E = EMAX;
    const int* src = ei;
    const int* dstp = ei + E;

    int nbE256 = (E + 255) / 256;
    int nbN128 = (N + 127) / 128;
    int nbE128 = (E + 127) / 128;

    k_pack<<<(PACKN + N + 255) / 256, 256>>>(msg_w1, msg_w2, upd_w1, upd_w2,
                                             out_w1, enc_w2, N);
    k_count<<<nbE256, 256>>>(dstp, E);
    k_encoder<<<nbN128, 256>>>(x, enc_w1, enc_b1, enc_b2, msg_b1, N);

    for (int l = 0; l < 3; l++) {
        k_edge<<<nbE128, 256>>>(src, dstp, l, msg_b2 + l * 64, E);
        k_upd<<<nbN128, 256>>>(l, upd_b1 + l * 64, upd_b2 + l * 64,
                               (l < 2) ? 1 : 0, msg_b1 + (l + 1) * 64,
                               out_b1, out_w2, out_b2, (float*)d_out, N);
    }
}